// round 3
// baseline (speedup 1.0000x reference)
#include <cuda_runtime.h>
#include <math.h>

#define HW    2560
#define TT    16
#define HEADS 8
#define DH    64
#define QD    512
#define MTOT  (HW * TT)      // 40960
#define SCALE 0.125f         // 64^-0.5

// ---------------- scratch (device globals: allocation-free) ----------------
__device__ float g_q[(size_t)MTOT * QD];
__device__ float g_k[(size_t)MTOT * QD];
__device__ float g_v[(size_t)MTOT * QD];
__device__ float g_att[(size_t)MTOT * QD];

// ---------------- GEMM: C[M,N] = A[M,K] @ B[K,N] (+ bias) -----------------
// 128x128 tile, BK=16, 256 threads, 8x8 microtile, float4 everywhere.
#define BM 128
#define BN 128
#define BK 16

__global__ __launch_bounds__(256)
void gemm128(const float* __restrict__ A, const float* __restrict__ B,
             const float* __restrict__ bias, float* __restrict__ C,
             int M, int N, int K) {
    __shared__ float As[BK][BM];       // transposed A tile
    __shared__ float Bs[BK][BN];

    const int tid = threadIdx.x;
    const int m0 = blockIdx.y * BM;
    const int n0 = blockIdx.x * BN;

    // A tile loads: 128 rows x 16 cols; thread covers rows (tid>>2) and +64
    const int ar = tid >> 2;            // 0..63
    const int ac = (tid & 3) * 4;       // 0,4,8,12
    // B tile loads: 16 rows x 128 cols; thread covers rows (tid>>5) and +8
    const int br = tid >> 5;            // 0..7
    const int bc = (tid & 31) * 4;      // 0..124

    const int ty = tid >> 4;            // 0..15
    const int tx = tid & 15;            // 0..15

    float acc[8][8];
#pragma unroll
    for (int i = 0; i < 8; i++)
#pragma unroll
        for (int j = 0; j < 8; j++) acc[i][j] = 0.0f;

    for (int k0 = 0; k0 < K; k0 += BK) {
#pragma unroll
        for (int rr = 0; rr < 2; rr++) {
            float4 a = *(const float4*)&A[(size_t)(m0 + ar + rr * 64) * K + k0 + ac];
            As[ac + 0][ar + rr * 64] = a.x;
            As[ac + 1][ar + rr * 64] = a.y;
            As[ac + 2][ar + rr * 64] = a.z;
            As[ac + 3][ar + rr * 64] = a.w;
        }
#pragma unroll
        for (int rr = 0; rr < 2; rr++) {
            float4 b = *(const float4*)&B[(size_t)(k0 + br + rr * 8) * N + n0 + bc];
            *(float4*)&Bs[br + rr * 8][bc] = b;
        }
        __syncthreads();

#pragma unroll
        for (int kk = 0; kk < BK; kk++) {
            float ra[8], rb[8];
            *(float4*)&ra[0] = *(const float4*)&As[kk][ty * 8];
            *(float4*)&ra[4] = *(const float4*)&As[kk][ty * 8 + 4];
            *(float4*)&rb[0] = *(const float4*)&Bs[kk][tx * 8];
            *(float4*)&rb[4] = *(const float4*)&Bs[kk][tx * 8 + 4];
#pragma unroll
            for (int i = 0; i < 8; i++)
#pragma unroll
                for (int j = 0; j < 8; j++)
                    acc[i][j] = fmaf(ra[i], rb[j], acc[i][j]);
        }
        __syncthreads();
    }

    float badd[8] = {0.f, 0.f, 0.f, 0.f, 0.f, 0.f, 0.f, 0.f};
    if (bias) {
#pragma unroll
        for (int j = 0; j < 8; j++) badd[j] = bias[n0 + tx * 8 + j];
    }
#pragma unroll
    for (int i = 0; i < 8; i++) {
        float4 o0, o1;
        o0.x = acc[i][0] + badd[0]; o0.y = acc[i][1] + badd[1];
        o0.z = acc[i][2] + badd[2]; o0.w = acc[i][3] + badd[3];
        o1.x = acc[i][4] + badd[4]; o1.y = acc[i][5] + badd[5];
        o1.z = acc[i][6] + badd[6]; o1.w = acc[i][7] + badd[7];
        float* cp = &C[(size_t)(m0 + ty * 8 + i) * N + n0 + tx * 8];
        *(float4*)cp = o0;
        *(float4*)(cp + 4) = o1;
    }
}

// ---------------- Attention core: one CTA per (hw, head) ------------------
struct Boxes { int hs[TT]; int ws[TT]; int sub_h; int sub_w; };

__global__ __launch_bounds__(128)
void attn_kernel(const float* __restrict__ Q, const float* __restrict__ K,
                 const float* __restrict__ V, const float* __restrict__ RK,
                 const float* __restrict__ RV, float* __restrict__ ATT,
                 Boxes bx) {
    const int hw = blockIdx.x;
    const int h  = blockIdx.y;
    const int tid = threadIdx.x;   // 128 threads

    __shared__ float qs[TT][DH];
    __shared__ float ks[TT][DH];
    __shared__ float vs[TT][DH];
    __shared__ float rk[33 * DH];
    __shared__ float rv[33 * DH];
    __shared__ float sims[TT][TT + 1];

    // stage q,k,v rows for this (hw, head)
    const size_t base = ((size_t)hw * TT) * QD + h * DH;
#pragma unroll
    for (int e = tid; e < TT * DH; e += 128) {
        int t = e >> 6, d = e & 63;
        size_t gi = base + (size_t)t * QD + d;
        qs[t][d] = Q[gi];
        ks[t][d] = K[gi];
        vs[t][d] = V[gi];
    }
    for (int e = tid; e < 33 * DH; e += 128) {
        rk[e] = RK[e];
        rv[e] = RV[e];
    }
    __syncthreads();

    // fg bitmask for this pixel
    const int y = hw / 40, x = hw % 40;
    unsigned fg = 0;
#pragma unroll
    for (int t = 0; t < TT; t++) {
        int inb = (y >= bx.hs[t]) & (y < bx.hs[t] + bx.sub_h) &
                  (x >= bx.ws[t]) & (x < bx.ws[t] + bx.sub_w);
        fg |= (unsigned)inb << t;
    }

    // sim = (q.k + q.rel_k) * SCALE * mask   (256 entries, 2 per thread)
#pragma unroll
    for (int e = tid; e < TT * TT; e += 128) {
        int i = e >> 4, j = e & 15;
        const float* rkp = &rk[(j - i + 16) * DH];
        float s = 0.0f, sr = 0.0f;
#pragma unroll
        for (int d = 0; d < DH; d++) {
            float qv = qs[i][d];
            s  = fmaf(qv, ks[j][d], s);
            sr = fmaf(qv, rkp[d], sr);
        }
        float m = (((fg >> i) & 1u) == ((fg >> j) & 1u)) ? 1.0f : 0.01f;
        sims[i][j] = (s + sr) * SCALE * m;
    }
    __syncthreads();

    // row softmax (16 rows, one thread each)
    if (tid < TT) {
        float mx = -1e30f;
#pragma unroll
        for (int j = 0; j < TT; j++) mx = fmaxf(mx, sims[tid][j]);
        float sum = 0.0f;
#pragma unroll
        for (int j = 0; j < TT; j++) {
            float e = expf(sims[tid][j] - mx);
            sims[tid][j] = e;
            sum += e;
        }
        float inv = 1.0f / sum;
#pragma unroll
        for (int j = 0; j < TT; j++) sims[tid][j] *= inv;
    }
    __syncthreads();

    // out[i][d] = sum_j attn[i][j] * (v[j][d] + rel_v[j-i+16][d])
#pragma unroll
    for (int e = tid; e < TT * DH; e += 128) {
        int i = e >> 6, d = e & 63;
        float o = 0.0f;
#pragma unroll
        for (int j = 0; j < TT; j++) {
            o = fmaf(sims[i][j], vs[j][d] + rv[(j - i + 16) * DH + d], o);
        }
        ATT[base + (size_t)i * QD + d] = o;
    }
}

// ---------------------------- launcher -------------------------------------
extern "C" void kernel_launch(void* const* d_in, const int* in_sizes, int n_in,
                              void* d_out, int out_size) {
    const float* x     = (const float*)d_in[0];
    const float* Wq    = (const float*)d_in[1];
    const float* Wk    = (const float*)d_in[2];
    const float* Wv    = (const float*)d_in[3];
    const float* Wo    = (const float*)d_in[4];
    const float* bo    = (const float*)d_in[5];
    const float* rel_k = (const float*)d_in[6];
    const float* rel_v = (const float*)d_in[7];
    float* out = (float*)d_out;

    float *q, *k, *v, *att;
    cudaGetSymbolAddress((void**)&q,   g_q);
    cudaGetSymbolAddress((void**)&k,   g_k);
    cudaGetSymbolAddress((void**)&v,   g_v);
    cudaGetSymbolAddress((void**)&att, g_att);

    // Box path: replicate the Python double-precision arithmetic exactly.
    // traj keyframes: [0, .10,.35,.10,.35] -> [15, .60,.85,.60,.85]
    // NOTE: in IEEE double, 0.35-0.10 = 0.25 - 2^-55, so:
    //   SUB_H = int((0.35-0.10)*64) = 15   (NOT 16)
    //   SUB_W = int((0.35-0.10)*40) = 9    (NOT 10)
    Boxes bx;
    bx.sub_h = (int)((0.35 - 0.10) * 64.0);
    bx.sub_w = (int)((0.35 - 0.10) * 40.0);
    for (int t = 0; t < TT; t++) {
        double r  = (double)t / 15.0;
        double h0 = 0.10 + r * (0.60 - 0.10);
        double w0 = 0.10 + r * (0.60 - 0.10);
        bx.hs[t] = (int)(h0 * 64.0);   // * H_LEN
        bx.ws[t] = (int)(w0 * 40.0);   // * W_LEN
    }

    dim3 gg(QD / BN, MTOT / BM);       // (4, 320)
    gemm128<<<gg, 256>>>(x, Wq, nullptr, q, MTOT, QD, QD);
    gemm128<<<gg, 256>>>(x, Wk, nullptr, k, MTOT, QD, QD);
    gemm128<<<gg, 256>>>(x, Wv, nullptr, v, MTOT, QD, QD);

    attn_kernel<<<dim3(HW, HEADS), 128>>>(q, k, v, rel_k, rel_v, att, bx);

    gemm128<<<gg, 256>>>(att, Wo, bo, out, MTOT, QD, QD);
}

// round 4
// speedup vs baseline: 1.1552x; 1.1552x over previous
#include <cuda_runtime.h>
#include <math.h>

#define HW    2560
#define TT    16
#define HEADS 8
#define DH    64
#define QD    512
#define MTOT  (HW * TT)      // 40960
#define SCALE 0.125f         // 64^-0.5

// ---------------- scratch (device globals: allocation-free) ----------------
__device__ float g_q[(size_t)MTOT * QD];
__device__ float g_k[(size_t)MTOT * QD];
__device__ float g_v[(size_t)MTOT * QD];
__device__ float g_att[(size_t)MTOT * QD];

// ---------------- GEMM: C[M,N] = A[M,K] @ B[K,N] (+ bias) -----------------
// 128x128 tile, BK=16, 256 threads, 8x8 microtile, float4 everywhere.
#define BM 128
#define BN 128
#define BK 16

__global__ __launch_bounds__(256)
void gemm128(const float* __restrict__ A, const float* __restrict__ B,
             const float* __restrict__ bias, float* __restrict__ C,
             int M, int N, int K) {
    __shared__ float As[BK][BM];       // transposed A tile
    __shared__ float Bs[BK][BN];

    const int tid = threadIdx.x;
    const int m0 = blockIdx.y * BM;
    const int n0 = blockIdx.x * BN;

    const int ar = tid >> 2;            // 0..63
    const int ac = (tid & 3) * 4;       // 0,4,8,12
    const int br = tid >> 5;            // 0..7
    const int bc = (tid & 31) * 4;      // 0..124

    const int ty = tid >> 4;            // 0..15
    const int tx = tid & 15;            // 0..15

    float acc[8][8];
#pragma unroll
    for (int i = 0; i < 8; i++)
#pragma unroll
        for (int j = 0; j < 8; j++) acc[i][j] = 0.0f;

    for (int k0 = 0; k0 < K; k0 += BK) {
#pragma unroll
        for (int rr = 0; rr < 2; rr++) {
            float4 a = *(const float4*)&A[(size_t)(m0 + ar + rr * 64) * K + k0 + ac];
            As[ac + 0][ar + rr * 64] = a.x;
            As[ac + 1][ar + rr * 64] = a.y;
            As[ac + 2][ar + rr * 64] = a.z;
            As[ac + 3][ar + rr * 64] = a.w;
        }
#pragma unroll
        for (int rr = 0; rr < 2; rr++) {
            float4 b = *(const float4*)&B[(size_t)(k0 + br + rr * 8) * N + n0 + bc];
            *(float4*)&Bs[br + rr * 8][bc] = b;
        }
        __syncthreads();

#pragma unroll
        for (int kk = 0; kk < BK; kk++) {
            float ra[8], rb[8];
            *(float4*)&ra[0] = *(const float4*)&As[kk][ty * 8];
            *(float4*)&ra[4] = *(const float4*)&As[kk][ty * 8 + 4];
            *(float4*)&rb[0] = *(const float4*)&Bs[kk][tx * 8];
            *(float4*)&rb[4] = *(const float4*)&Bs[kk][tx * 8 + 4];
#pragma unroll
            for (int i = 0; i < 8; i++)
#pragma unroll
                for (int j = 0; j < 8; j++)
                    acc[i][j] = fmaf(ra[i], rb[j], acc[i][j]);
        }
        __syncthreads();
    }

    float badd[8] = {0.f, 0.f, 0.f, 0.f, 0.f, 0.f, 0.f, 0.f};
    if (bias) {
#pragma unroll
        for (int j = 0; j < 8; j++) badd[j] = bias[n0 + tx * 8 + j];
    }
#pragma unroll
    for (int i = 0; i < 8; i++) {
        float4 o0, o1;
        o0.x = acc[i][0] + badd[0]; o0.y = acc[i][1] + badd[1];
        o0.z = acc[i][2] + badd[2]; o0.w = acc[i][3] + badd[3];
        o1.x = acc[i][4] + badd[4]; o1.y = acc[i][5] + badd[5];
        o1.z = acc[i][6] + badd[6]; o1.w = acc[i][7] + badd[7];
        float* cp = &C[(size_t)(m0 + ty * 8 + i) * N + n0 + tx * 8];
        *(float4*)cp = o0;
        *(float4*)(cp + 4) = o1;
    }
}

// ---------------- Attention core: one CTA per (hw, head), 256 threads ------
// Bank-conflict-free smem layout:
//   qs  [TT][65]  : q rows padded to 65 words -> adjacent i in different banks
//   kst [DH][17]  : K transposed -> warp's 16 j values hit 16 distinct banks
//   rkt [DH][34]  : rel_k transposed -> 17 consecutive addrs, conflict-free
//   vs  [TT][DH]  : row access in output loop, conflict-free
//   rvs [33][DH]  : row access in output loop, conflict-free
struct Boxes { int hs[TT]; int ws[TT]; int sub_h; int sub_w; };

__global__ __launch_bounds__(256)
void attn_kernel(const float* __restrict__ Q, const float* __restrict__ K,
                 const float* __restrict__ V, const float* __restrict__ RK,
                 const float* __restrict__ RV, float* __restrict__ ATT,
                 Boxes bx) {
    const int hw = blockIdx.x;
    const int h  = blockIdx.y;
    const int tid = threadIdx.x;   // 256 threads

    __shared__ float qs[TT][DH + 1];
    __shared__ float kst[DH][TT + 1];
    __shared__ float vs[TT][DH];
    __shared__ float rkt[DH][34];
    __shared__ float rvs[33][DH];
    __shared__ float sims[TT][TT + 1];

    // stage q,k,v rows for this (hw, head); k transposed
    const size_t base = ((size_t)hw * TT) * QD + h * DH;
#pragma unroll
    for (int e = tid; e < TT * DH; e += 256) {
        int t = e >> 6, d = e & 63;
        size_t gi = base + (size_t)t * QD + d;
        qs[t][d]  = Q[gi];
        kst[d][t] = K[gi];
        vs[t][d]  = V[gi];
    }
#pragma unroll
    for (int e = tid; e < 33 * DH; e += 256) {
        int r = e >> 6, d = e & 63;
        rkt[d][r] = RK[e];
        rvs[r][d] = RV[e];
    }
    __syncthreads();

    // fg bitmask for this pixel
    const int y = hw / 40, x = hw % 40;
    unsigned fg = 0;
#pragma unroll
    for (int t = 0; t < TT; t++) {
        int inb = (y >= bx.hs[t]) & (y < bx.hs[t] + bx.sub_h) &
                  (x >= bx.ws[t]) & (x < bx.ws[t] + bx.sub_w);
        fg |= (unsigned)inb << t;
    }

    // sim = (q.k + q.rel_k) * SCALE * mask   (one (i,j) entry per thread)
    {
        const int i = tid >> 4, j = tid & 15;
        const int r = j - i + 16;
        float s = 0.0f, sr = 0.0f;
#pragma unroll
        for (int d = 0; d < DH; d++) {
            float qv = qs[i][d];
            s  = fmaf(qv, kst[d][j], s);
            sr = fmaf(qv, rkt[d][r], sr);
        }
        float m = (((fg >> i) & 1u) == ((fg >> j) & 1u)) ? 1.0f : 0.01f;
        sims[i][j] = (s + sr) * SCALE * m;
    }
    __syncthreads();

    // row softmax (16 rows, one thread each)
    if (tid < TT) {
        float mx = -1e30f;
#pragma unroll
        for (int j = 0; j < TT; j++) mx = fmaxf(mx, sims[tid][j]);
        float sum = 0.0f;
#pragma unroll
        for (int j = 0; j < TT; j++) {
            float e = expf(sims[tid][j] - mx);
            sims[tid][j] = e;
            sum += e;
        }
        float inv = 1.0f / sum;
#pragma unroll
        for (int j = 0; j < TT; j++) sims[tid][j] *= inv;
    }
    __syncthreads();

    // out[i][d] = sum_j attn[i][j] * (v[j][d] + rel_v[j-i+16][d])
#pragma unroll
    for (int e = tid; e < TT * DH; e += 256) {
        int i = e >> 6, d = e & 63;
        float o = 0.0f;
#pragma unroll
        for (int j = 0; j < TT; j++) {
            o = fmaf(sims[i][j], vs[j][d] + rvs[j - i + 16][d], o);
        }
        ATT[base + (size_t)i * QD + d] = o;
    }
}

// ---------------------------- launcher -------------------------------------
extern "C" void kernel_launch(void* const* d_in, const int* in_sizes, int n_in,
                              void* d_out, int out_size) {
    const float* x     = (const float*)d_in[0];
    const float* Wq    = (const float*)d_in[1];
    const float* Wk    = (const float*)d_in[2];
    const float* Wv    = (const float*)d_in[3];
    const float* Wo    = (const float*)d_in[4];
    const float* bo    = (const float*)d_in[5];
    const float* rel_k = (const float*)d_in[6];
    const float* rel_v = (const float*)d_in[7];
    float* out = (float*)d_out;

    float *q, *k, *v, *att;
    cudaGetSymbolAddress((void**)&q,   g_q);
    cudaGetSymbolAddress((void**)&k,   g_k);
    cudaGetSymbolAddress((void**)&v,   g_v);
    cudaGetSymbolAddress((void**)&att, g_att);

    // Box path: replicate the Python double-precision arithmetic exactly.
    // In IEEE double, 0.35-0.10 = 0.25 - 2^-55, so:
    //   SUB_H = int((0.35-0.10)*64) = 15,  SUB_W = int((0.35-0.10)*40) = 9
    Boxes bx;
    bx.sub_h = (int)((0.35 - 0.10) * 64.0);
    bx.sub_w = (int)((0.35 - 0.10) * 40.0);
    for (int t = 0; t < TT; t++) {
        double r  = (double)t / 15.0;
        double h0 = 0.10 + r * (0.60 - 0.10);
        double w0 = 0.10 + r * (0.60 - 0.10);
        bx.hs[t] = (int)(h0 * 64.0);   // * H_LEN
        bx.ws[t] = (int)(w0 * 40.0);   // * W_LEN
    }

    dim3 gg(QD / BN, MTOT / BM);       // (4, 320)
    gemm128<<<gg, 256>>>(x, Wq, nullptr, q, MTOT, QD, QD);
    gemm128<<<gg, 256>>>(x, Wk, nullptr, k, MTOT, QD, QD);
    gemm128<<<gg, 256>>>(x, Wv, nullptr, v, MTOT, QD, QD);

    attn_kernel<<<dim3(HW, HEADS), 256>>>(q, k, v, rel_k, rel_v, att, bx);

    gemm128<<<gg, 256>>>(att, Wo, bo, out, MTOT, QD, QD);
}

// round 7
// speedup vs baseline: 1.6885x; 1.4616x over previous
#include <cuda_runtime.h>
#include <cuda_bf16.h>
#include <math.h>
#include <stdint.h>

#define HW    2560
#define TT    16
#define HEADS 8
#define DH    64
#define QD    512
#define MTOT  (HW * TT)      // 40960
#define SCALE 0.125f         // 64^-0.5

// ---------------- scratch (device globals: allocation-free) ----------------
__device__ float g_q[(size_t)MTOT * QD];
__device__ float g_k[(size_t)MTOT * QD];
__device__ float g_v[(size_t)MTOT * QD];
__device__ float g_att[(size_t)MTOT * QD];

// ---------------- warp-MMA helper: m16n8k16 bf16 -> f32 --------------------
__device__ __forceinline__ void mma16816(float* d, const uint32_t* a, const uint32_t* b) {
    asm volatile(
        "mma.sync.aligned.m16n8k16.row.col.f32.bf16.bf16.f32 "
        "{%0,%1,%2,%3}, {%4,%5,%6,%7}, {%8,%9}, {%0,%1,%2,%3};"
        : "+f"(d[0]), "+f"(d[1]), "+f"(d[2]), "+f"(d[3])
        : "r"(a[0]), "r"(a[1]), "r"(a[2]), "r"(a[3]), "r"(b[0]), "r"(b[1]));
}

// ======== split-bf16 tensor-core GEMM: C[M,512] = A[M,512] @ W[512,512] ====
// A = Ah + Al, W = Bh + Bl (bf16 Dekker split); C = Ah*Bh + Ah*Bl + Al*Bh,
// fp32 accumulation in mma.sync. CTA tile 128x128, BK=32, 8 warps (4m x 2n),
// warp tile 32x64 = 2 m-frags x 8 n-frags of m16n8k16.
#define BKC 32
#define SPAD 40   // row stride in bf16 (20 banks -> conflict-free frag loads)

__global__ __launch_bounds__(256, 2)
void gemm_mma(const float* __restrict__ A, const float* __restrict__ W,
              const float* __restrict__ bias, float* __restrict__ C) {
    __shared__ __nv_bfloat16 As_h[128][SPAD];
    __shared__ __nv_bfloat16 As_l[128][SPAD];
    __shared__ __nv_bfloat16 Bs_h[128][SPAD];   // Bs[n][k]
    __shared__ __nv_bfloat16 Bs_l[128][SPAD];

    const int tid = threadIdx.x;
    const int wid = tid >> 5, lid = tid & 31;
    const int wm = wid & 3, wn = wid >> 2;      // warp grid 4(m) x 2(n)
    const int g = lid >> 2, t = lid & 3;        // groupID, threadInGroup
    const int m0 = blockIdx.y * 128;
    const int n0 = blockIdx.x * 128;

    float acc[2][8][4];
#pragma unroll
    for (int mi = 0; mi < 2; mi++)
#pragma unroll
        for (int ni = 0; ni < 8; ni++)
#pragma unroll
            for (int c = 0; c < 4; c++) acc[mi][ni][c] = 0.0f;

    for (int kc = 0; kc < QD / BKC; kc++) {
        // ---- stage A [128 x 32] fp32 -> hi/lo bf16 ----
#pragma unroll
        for (int i = 0; i < 8; i++) {
            int e = tid + i * 256;
            int row = e >> 4, cp = e & 15;
            float2 a2 = *(const float2*)&A[(size_t)(m0 + row) * QD + kc * BKC + cp * 2];
            __nv_bfloat16 hx = __float2bfloat16(a2.x);
            __nv_bfloat16 hy = __float2bfloat16(a2.y);
            __nv_bfloat16 lx = __float2bfloat16(a2.x - __bfloat162float(hx));
            __nv_bfloat16 ly = __float2bfloat16(a2.y - __bfloat162float(hy));
            *(__nv_bfloat162*)&As_h[row][cp * 2] = __halves2bfloat162(hx, hy);
            *(__nv_bfloat162*)&As_l[row][cp * 2] = __halves2bfloat162(lx, ly);
        }
        // ---- stage B: Bs[n][k] = W[kc*32+k][n0+n], hi/lo ----
#pragma unroll
        for (int i = 0; i < 8; i++) {
            int e = tid + i * 256;
            int k = e >> 6, np = e & 63;
            float2 w2 = *(const float2*)&W[(size_t)(kc * BKC + k) * QD + n0 + np * 2];
            __nv_bfloat16 hx = __float2bfloat16(w2.x);
            __nv_bfloat16 hy = __float2bfloat16(w2.y);
            __nv_bfloat16 lx = __float2bfloat16(w2.x - __bfloat162float(hx));
            __nv_bfloat16 ly = __float2bfloat16(w2.y - __bfloat162float(hy));
            Bs_h[np * 2][k]     = hx;
            Bs_h[np * 2 + 1][k] = hy;
            Bs_l[np * 2][k]     = lx;
            Bs_l[np * 2 + 1][k] = ly;
        }
        __syncthreads();

#pragma unroll
        for (int ks = 0; ks < 2; ks++) {
            const int c0 = ks * 16 + t * 2;
            uint32_t bh[8][2], bl[8][2];
#pragma unroll
            for (int ni = 0; ni < 8; ni++) {
                int n = wn * 64 + ni * 8 + g;
                bh[ni][0] = *(const uint32_t*)&Bs_h[n][c0];
                bh[ni][1] = *(const uint32_t*)&Bs_h[n][c0 + 8];
                bl[ni][0] = *(const uint32_t*)&Bs_l[n][c0];
                bl[ni][1] = *(const uint32_t*)&Bs_l[n][c0 + 8];
            }
#pragma unroll
            for (int mi = 0; mi < 2; mi++) {
                int r = wm * 32 + mi * 16 + g;
                uint32_t ah[4], al[4];
                ah[0] = *(const uint32_t*)&As_h[r][c0];
                ah[1] = *(const uint32_t*)&As_h[r + 8][c0];
                ah[2] = *(const uint32_t*)&As_h[r][c0 + 8];
                ah[3] = *(const uint32_t*)&As_h[r + 8][c0 + 8];
                al[0] = *(const uint32_t*)&As_l[r][c0];
                al[1] = *(const uint32_t*)&As_l[r + 8][c0];
                al[2] = *(const uint32_t*)&As_l[r][c0 + 8];
                al[3] = *(const uint32_t*)&As_l[r + 8][c0 + 8];
#pragma unroll
                for (int ni = 0; ni < 8; ni++) {
                    mma16816(acc[mi][ni], ah, bh[ni]);
                    mma16816(acc[mi][ni], ah, bl[ni]);
                    mma16816(acc[mi][ni], al, bh[ni]);
                }
            }
        }
        __syncthreads();
    }

    // ---- epilogue: fragment -> gmem (float2, 32B-coalesced per group) ----
#pragma unroll
    for (int mi = 0; mi < 2; mi++) {
        int r = m0 + wm * 32 + mi * 16 + g;
#pragma unroll
        for (int ni = 0; ni < 8; ni++) {
            int col = n0 + wn * 64 + ni * 8 + t * 2;
            float b0 = 0.f, b1 = 0.f;
            if (bias) { b0 = bias[col]; b1 = bias[col + 1]; }
            float2 v0, v1;
            v0.x = acc[mi][ni][0] + b0; v0.y = acc[mi][ni][1] + b1;
            v1.x = acc[mi][ni][2] + b0; v1.y = acc[mi][ni][3] + b1;
            *(float2*)&C[(size_t)r * QD + col] = v0;
            *(float2*)&C[(size_t)(r + 8) * QD + col] = v1;
        }
    }
}

// ---------------- Attention core: one CTA per (hw, head), 256 threads ------
struct Boxes { int hs[TT]; int ws[TT]; int sub_h; int sub_w; };

__global__ __launch_bounds__(256)
void attn_kernel(const float* __restrict__ Q, const float* __restrict__ K,
                 const float* __restrict__ V, const float* __restrict__ RK,
                 const float* __restrict__ RV, float* __restrict__ ATT,
                 Boxes bx) {
    const int hw = blockIdx.x;
    const int h  = blockIdx.y;
    const int tid = threadIdx.x;   // 256 threads

    __shared__ float qs[TT][DH + 1];
    __shared__ float kst[DH][TT + 1];
    __shared__ float vs[TT][DH];
    __shared__ float rkt[DH][34];
    __shared__ float rvs[33][DH];
    __shared__ float sims[TT][TT + 1];

    const size_t base = ((size_t)hw * TT) * QD + h * DH;
#pragma unroll
    for (int e = tid; e < TT * DH; e += 256) {
        int t = e >> 6, d = e & 63;
        size_t gi = base + (size_t)t * QD + d;
        qs[t][d]  = Q[gi];
        kst[d][t] = K[gi];
        vs[t][d]  = V[gi];
    }
#pragma unroll
    for (int e = tid; e < 33 * DH; e += 256) {
        int r = e >> 6, d = e & 63;
        rkt[d][r] = RK[e];
        rvs[r][d] = RV[e];
    }
    __syncthreads();

    const int y = hw / 40, x = hw % 40;
    unsigned fg = 0;
#pragma unroll
    for (int t = 0; t < TT; t++) {
        int inb = (y >= bx.hs[t]) & (y < bx.hs[t] + bx.sub_h) &
                  (x >= bx.ws[t]) & (x < bx.ws[t] + bx.sub_w);
        fg |= (unsigned)inb << t;
    }

    {
        const int i = tid >> 4, j = tid & 15;
        const int r = j - i + 16;
        float s = 0.0f, sr = 0.0f;
#pragma unroll
        for (int d = 0; d < DH; d++) {
            float qv = qs[i][d];
            s  = fmaf(qv, kst[d][j], s);
            sr = fmaf(qv, rkt[d][r], sr);
        }
        float m = (((fg >> i) & 1u) == ((fg >> j) & 1u)) ? 1.0f : 0.01f;
        sims[i][j] = (s + sr) * SCALE * m;
    }
    __syncthreads();

    if (tid < TT) {
        float mx = -1e30f;
#pragma unroll
        for (int j = 0; j < TT; j++) mx = fmaxf(mx, sims[tid][j]);
        float sum = 0.0f;
#pragma unroll
        for (int j = 0; j < TT; j++) {
            float e = expf(sims[tid][j] - mx);
            sims[tid][j] = e;
            sum += e;
        }
        float inv = 1.0f / sum;
#pragma unroll
        for (int j = 0; j < TT; j++) sims[tid][j] *= inv;
    }
    __syncthreads();

#pragma unroll
    for (int e = tid; e < TT * DH; e += 256) {
        int i = e >> 6, d = e & 63;
        float o = 0.0f;
#pragma unroll
        for (int j = 0; j < TT; j++) {
            o = fmaf(sims[i][j], vs[j][d] + rvs[j - i + 16][d], o);
        }
        ATT[base + (size_t)i * QD + d] = o;
    }
}

// ---------------------------- launcher -------------------------------------
extern "C" void kernel_launch(void* const* d_in, const int* in_sizes, int n_in,
                              void* d_out, int out_size) {
    const float* x     = (const float*)d_in[0];
    const float* Wq    = (const float*)d_in[1];
    const float* Wk    = (const float*)d_in[2];
    const float* Wv    = (const float*)d_in[3];
    const float* Wo    = (const float*)d_in[4];
    const float* bo    = (const float*)d_in[5];
    const float* rel_k = (const float*)d_in[6];
    const float* rel_v = (const float*)d_in[7];
    float* out = (float*)d_out;

    float *q, *k, *v, *att;
    cudaGetSymbolAddress((void**)&q,   g_q);
    cudaGetSymbolAddress((void**)&k,   g_k);
    cudaGetSymbolAddress((void**)&v,   g_v);
    cudaGetSymbolAddress((void**)&att, g_att);

    // Box path (exact binary64 semantics): SUB_H=15, SUB_W=9
    Boxes bx;
    bx.sub_h = (int)((0.35 - 0.10) * 64.0);
    bx.sub_w = (int)((0.35 - 0.10) * 40.0);
    for (int t = 0; t < TT; t++) {
        double r  = (double)t / 15.0;
        double h0 = 0.10 + r * (0.60 - 0.10);
        double w0 = 0.10 + r * (0.60 - 0.10);
        bx.hs[t] = (int)(h0 * 64.0);
        bx.ws[t] = (int)(w0 * 40.0);
    }

    dim3 gg(QD / 128, MTOT / 128);     // (4, 320)
    gemm_mma<<<gg, 256>>>(x, Wq, nullptr, q);
    gemm_mma<<<gg, 256>>>(x, Wk, nullptr, k);
    gemm_mma<<<gg, 256>>>(x, Wv, nullptr, v);

    attn_kernel<<<dim3(HW, HEADS), 256>>>(q, k, v, rel_k, rel_v, att, bx);

    gemm_mma<<<gg, 256>>>(att, Wo, bo, out);
}

// round 8
// speedup vs baseline: 2.4250x; 1.4362x over previous
#include <cuda_runtime.h>
#include <cuda_bf16.h>
#include <math.h>
#include <stdint.h>

#define HW    2560
#define TT    16
#define HEADS 8
#define DH    64
#define QD    512
#define MTOT  (HW * TT)      // 40960
#define SCALE 0.125f         // 64^-0.5

// ---------------- scratch (device globals: allocation-free) ----------------
__device__ float g_q[(size_t)MTOT * QD];
__device__ float g_k[(size_t)MTOT * QD];
__device__ float g_v[(size_t)MTOT * QD];
__device__ __nv_bfloat16 g_xh[(size_t)MTOT * QD];
__device__ __nv_bfloat16 g_xl[(size_t)MTOT * QD];
__device__ __nv_bfloat16 g_ath[(size_t)MTOT * QD];
__device__ __nv_bfloat16 g_atl[(size_t)MTOT * QD];
__device__ __nv_bfloat16 g_wth[(size_t)4 * QD * QD];   // Wt[w][n][k] hi
__device__ __nv_bfloat16 g_wtl[(size_t)4 * QD * QD];   // Wt[w][n][k] lo

// ---------------- helpers --------------------------------------------------
__device__ __forceinline__ uint32_t smem_u32(const void* p) {
    uint32_t a;
    asm("{ .reg .u64 t; cvta.to.shared.u64 t, %1; cvt.u32.u64 %0, t; }" : "=r"(a) : "l"(p));
    return a;
}
__device__ __forceinline__ void mma16816(float* d, const uint32_t* a, const uint32_t* b) {
    asm volatile(
        "mma.sync.aligned.m16n8k16.row.col.f32.bf16.bf16.f32 "
        "{%0,%1,%2,%3}, {%4,%5,%6,%7}, {%8,%9}, {%0,%1,%2,%3};"
        : "+f"(d[0]), "+f"(d[1]), "+f"(d[2]), "+f"(d[3])
        : "r"(a[0]), "r"(a[1]), "r"(a[2]), "r"(a[3]), "r"(b[0]), "r"(b[1]));
}
__device__ __forceinline__ void cp16(uint32_t dst, const void* src) {
    asm volatile("cp.async.ca.shared.global [%0], [%1], 16;" :: "r"(dst), "l"(src));
}
#define CP_COMMIT() asm volatile("cp.async.commit_group;" ::: "memory")
#define CP_WAIT1()  asm volatile("cp.async.wait_group 1;" ::: "memory")
#define CP_WAIT0()  asm volatile("cp.async.wait_group 0;" ::: "memory")

// ---------------- split passes ---------------------------------------------
__global__ __launch_bounds__(256)
void split_x(const float* __restrict__ X, __nv_bfloat16* __restrict__ xh,
             __nv_bfloat16* __restrict__ xl) {
    size_t i = (size_t)blockIdx.x * 256 + threadIdx.x;   // over MTOT*QD/2
    float2 a = ((const float2*)X)[i];
    __nv_bfloat16 hx = __float2bfloat16(a.x);
    __nv_bfloat16 hy = __float2bfloat16(a.y);
    __nv_bfloat16 lx = __float2bfloat16(a.x - __bfloat162float(hx));
    __nv_bfloat16 ly = __float2bfloat16(a.y - __bfloat162float(hy));
    ((__nv_bfloat162*)xh)[i] = __halves2bfloat162(hx, hy);
    ((__nv_bfloat162*)xl)[i] = __halves2bfloat162(lx, ly);
}

// transpose+split the 4 weight matrices: Wt[w][n][k] = W[k][n]
__global__ __launch_bounds__(256)
void split_w(const float* __restrict__ W0, const float* __restrict__ W1,
             const float* __restrict__ W2, const float* __restrict__ W3,
             __nv_bfloat16* __restrict__ wh, __nv_bfloat16* __restrict__ wl) {
    __shared__ float t[32][33];
    const int w = blockIdx.z;
    const float* W = (w == 0) ? W0 : (w == 1) ? W1 : (w == 2) ? W2 : W3;
    const int tx = threadIdx.x, ty = threadIdx.y;   // (32, 8)
#pragma unroll
    for (int i = 0; i < 4; i++)
        t[ty + 8 * i][tx] = W[(size_t)(blockIdx.y * 32 + ty + 8 * i) * QD + blockIdx.x * 32 + tx];
    __syncthreads();
#pragma unroll
    for (int i = 0; i < 4; i++) {
        int n = blockIdx.x * 32 + ty + 8 * i;
        int k = blockIdx.y * 32 + tx;
        float v = t[tx][ty + 8 * i];
        __nv_bfloat16 h = __float2bfloat16(v);
        __nv_bfloat16 l = __float2bfloat16(v - __bfloat162float(h));
        size_t o = ((size_t)w * QD + n) * QD + k;
        wh[o] = h;
        wl[o] = l;
    }
}

// ======== double-buffered split-bf16 GEMM: C[M,512] = A @ W (+bias) ========
#define BKC   32
#define SPAD  40                    // bf16 row stride (80 B)
#define TILEB (128 * SPAD * 2)      // 10240 B per tile
#define BUFB  (4 * TILEB)           // 40960 B per stage
#define GDYN  (2 * BUFB)            // 81920 B

__device__ __forceinline__ void gemm_prefetch(
    uint32_t sbase, int b, int kc, int tid, int m0, int n0,
    const __nv_bfloat16* Ah, const __nv_bfloat16* Al,
    const __nv_bfloat16* Bh, const __nv_bfloat16* Bl) {
#pragma unroll
    for (int i = 0; i < 8; i++) {
        int e = tid + i * 256;
        int tile = e >> 9;
        int r    = (e >> 2) & 127;
        int c16  = e & 3;
        uint32_t dst = sbase + b * BUFB + tile * TILEB + r * 80 + c16 * 16;
        const __nv_bfloat16* src;
        if (tile == 0)      src = Ah + (size_t)(m0 + r) * QD + kc * BKC + c16 * 8;
        else if (tile == 1) src = Al + (size_t)(m0 + r) * QD + kc * BKC + c16 * 8;
        else if (tile == 2) src = Bh + (size_t)(n0 + r) * QD + kc * BKC + c16 * 8;
        else                src = Bl + (size_t)(n0 + r) * QD + kc * BKC + c16 * 8;
        cp16(dst, src);
    }
    CP_COMMIT();
}

__global__ __launch_bounds__(256, 2)
void gemm_bf(const __nv_bfloat16* __restrict__ Ah, const __nv_bfloat16* __restrict__ Al,
             const __nv_bfloat16* __restrict__ Wth, const __nv_bfloat16* __restrict__ Wtl,
             const float* __restrict__ bias,
             float* __restrict__ C0, float* __restrict__ C1, float* __restrict__ C2) {
    extern __shared__ char dsm[];
    const uint32_t sbase = smem_u32(dsm);

    const int tid = threadIdx.x;
    const int wid = tid >> 5, lid = tid & 31;
    const int wm = wid & 3, wn = wid >> 2;      // warp grid 4(m) x 2(n)
    const int g = lid >> 2, t = lid & 3;
    const int m0 = blockIdx.y * 128;
    const int n0 = blockIdx.x * 128;
    const int w  = blockIdx.z;
    float* C = (w == 0) ? C0 : (w == 1) ? C1 : C2;
    const __nv_bfloat16* Bh = Wth + (size_t)w * QD * QD;
    const __nv_bfloat16* Bl = Wtl + (size_t)w * QD * QD;

    float acc[2][8][4];
#pragma unroll
    for (int mi = 0; mi < 2; mi++)
#pragma unroll
        for (int ni = 0; ni < 8; ni++)
#pragma unroll
            for (int c = 0; c < 4; c++) acc[mi][ni][c] = 0.0f;

    gemm_prefetch(sbase, 0, 0, tid, m0, n0, Ah, Al, Bh, Bl);

    for (int kc = 0; kc < QD / BKC; kc++) {
        const int last = (kc == QD / BKC - 1);
        if (!last) gemm_prefetch(sbase, (kc + 1) & 1, kc + 1, tid, m0, n0, Ah, Al, Bh, Bl);
        if (!last) CP_WAIT1(); else CP_WAIT0();
        __syncthreads();

        const int b = kc & 1;
        const __nv_bfloat16* As_h = (const __nv_bfloat16*)(dsm + b * BUFB);
        const __nv_bfloat16* As_l = (const __nv_bfloat16*)(dsm + b * BUFB + TILEB);
        const __nv_bfloat16* Bs_h = (const __nv_bfloat16*)(dsm + b * BUFB + 2 * TILEB);
        const __nv_bfloat16* Bs_l = (const __nv_bfloat16*)(dsm + b * BUFB + 3 * TILEB);

#pragma unroll
        for (int ks = 0; ks < 2; ks++) {
            const int c0 = ks * 16 + t * 2;
            uint32_t bh[8][2], bl[8][2];
#pragma unroll
            for (int ni = 0; ni < 8; ni++) {
                int n = wn * 64 + ni * 8 + g;
                bh[ni][0] = *(const uint32_t*)&Bs_h[n * SPAD + c0];
                bh[ni][1] = *(const uint32_t*)&Bs_h[n * SPAD + c0 + 8];
                bl[ni][0] = *(const uint32_t*)&Bs_l[n * SPAD + c0];
                bl[ni][1] = *(const uint32_t*)&Bs_l[n * SPAD + c0 + 8];
            }
#pragma unroll
            for (int mi = 0; mi < 2; mi++) {
                int r = wm * 32 + mi * 16 + g;
                uint32_t ah[4], al[4];
                ah[0] = *(const uint32_t*)&As_h[r * SPAD + c0];
                ah[1] = *(const uint32_t*)&As_h[(r + 8) * SPAD + c0];
                ah[2] = *(const uint32_t*)&As_h[r * SPAD + c0 + 8];
                ah[3] = *(const uint32_t*)&As_h[(r + 8) * SPAD + c0 + 8];
                al[0] = *(const uint32_t*)&As_l[r * SPAD + c0];
                al[1] = *(const uint32_t*)&As_l[(r + 8) * SPAD + c0];
                al[2] = *(const uint32_t*)&As_l[r * SPAD + c0 + 8];
                al[3] = *(const uint32_t*)&As_l[(r + 8) * SPAD + c0 + 8];
#pragma unroll
                for (int ni = 0; ni < 8; ni++) {
                    mma16816(acc[mi][ni], ah, bh[ni]);
                    mma16816(acc[mi][ni], ah, bl[ni]);
                    mma16816(acc[mi][ni], al, bh[ni]);
                }
            }
        }
        __syncthreads();
    }

    // ---- epilogue ----
#pragma unroll
    for (int mi = 0; mi < 2; mi++) {
        int r = m0 + wm * 32 + mi * 16 + g;
#pragma unroll
        for (int ni = 0; ni < 8; ni++) {
            int col = n0 + wn * 64 + ni * 8 + t * 2;
            float b0 = 0.f, b1 = 0.f;
            if (bias) { b0 = bias[col]; b1 = bias[col + 1]; }
            float2 v0, v1;
            v0.x = acc[mi][ni][0] + b0; v0.y = acc[mi][ni][1] + b1;
            v1.x = acc[mi][ni][2] + b0; v1.y = acc[mi][ni][3] + b1;
            *(float2*)&C[(size_t)r * QD + col] = v0;
            *(float2*)&C[(size_t)(r + 8) * QD + col] = v1;
        }
    }
}

// ---------------- Attention core: one CTA per (hw, head), 256 threads ------
struct Boxes { int hs[TT]; int ws[TT]; int sub_h; int sub_w; };

__global__ __launch_bounds__(256)
void attn_kernel(const float* __restrict__ Q, const float* __restrict__ K,
                 const float* __restrict__ V, const float* __restrict__ RK,
                 const float* __restrict__ RV,
                 __nv_bfloat16* __restrict__ ATH, __nv_bfloat16* __restrict__ ATL,
                 Boxes bx) {
    const int hw = blockIdx.x;
    const int h  = blockIdx.y;
    const int tid = threadIdx.x;

    __shared__ float qs[TT][DH + 1];
    __shared__ float kst[DH][TT + 1];
    __shared__ float vs[TT][DH];
    __shared__ float rkt[DH][34];
    __shared__ float rvs[33][DH];
    __shared__ float sims[TT][TT + 1];

    const size_t base = ((size_t)hw * TT) * QD + h * DH;
#pragma unroll
    for (int e = tid; e < TT * DH; e += 256) {
        int t = e >> 6, d = e & 63;
        size_t gi = base + (size_t)t * QD + d;
        qs[t][d]  = Q[gi];
        kst[d][t] = K[gi];
        vs[t][d]  = V[gi];
    }
#pragma unroll
    for (int e = tid; e < 33 * DH; e += 256) {
        int r = e >> 6, d = e & 63;
        rkt[d][r] = RK[e];
        rvs[r][d] = RV[e];
    }
    __syncthreads();

    const int y = hw / 40, x = hw % 40;
    unsigned fg = 0;
#pragma unroll
    for (int t = 0; t < TT; t++) {
        int inb = (y >= bx.hs[t]) & (y < bx.hs[t] + bx.sub_h) &
                  (x >= bx.ws[t]) & (x < bx.ws[t] + bx.sub_w);
        fg |= (unsigned)inb << t;
    }

    {
        const int i = tid >> 4, j = tid & 15;
        const int r = j - i + 16;
        float s = 0.0f, sr = 0.0f;
#pragma unroll
        for (int d = 0; d < DH; d++) {
            float qv = qs[i][d];
            s  = fmaf(qv, kst[d][j], s);
            sr = fmaf(qv, rkt[d][r], sr);
        }
        float m = (((fg >> i) & 1u) == ((fg >> j) & 1u)) ? 1.0f : 0.01f;
        sims[i][j] = (s + sr) * SCALE * m;
    }
    __syncthreads();

    if (tid < TT) {
        float mx = -1e30f;
#pragma unroll
        for (int j = 0; j < TT; j++) mx = fmaxf(mx, sims[tid][j]);
        float sum = 0.0f;
#pragma unroll
        for (int j = 0; j < TT; j++) {
            float e = expf(sims[tid][j] - mx);
            sims[tid][j] = e;
            sum += e;
        }
        float inv = 1.0f / sum;
#pragma unroll
        for (int j = 0; j < TT; j++) sims[tid][j] *= inv;
    }
    __syncthreads();

#pragma unroll
    for (int e = tid; e < TT * DH; e += 256) {
        int i = e >> 6, d = e & 63;
        float o = 0.0f;
#pragma unroll
        for (int j = 0; j < TT; j++) {
            o = fmaf(sims[i][j], vs[j][d] + rvs[j - i + 16][d], o);
        }
        __nv_bfloat16 oh = __float2bfloat16(o);
        __nv_bfloat16 ol = __float2bfloat16(o - __bfloat162float(oh));
        ATH[base + (size_t)i * QD + d] = oh;
        ATL[base + (size_t)i * QD + d] = ol;
    }
}

// ---------------------------- launcher -------------------------------------
extern "C" void kernel_launch(void* const* d_in, const int* in_sizes, int n_in,
                              void* d_out, int out_size) {
    const float* x     = (const float*)d_in[0];
    const float* Wq    = (const float*)d_in[1];
    const float* Wk    = (const float*)d_in[2];
    const float* Wv    = (const float*)d_in[3];
    const float* Wo    = (const float*)d_in[4];
    const float* bo    = (const float*)d_in[5];
    const float* rel_k = (const float*)d_in[6];
    const float* rel_v = (const float*)d_in[7];
    float* out = (float*)d_out;

    float *q, *k, *v;
    __nv_bfloat16 *xh, *xl, *ath, *atl, *wth, *wtl;
    cudaGetSymbolAddress((void**)&q,   g_q);
    cudaGetSymbolAddress((void**)&k,   g_k);
    cudaGetSymbolAddress((void**)&v,   g_v);
    cudaGetSymbolAddress((void**)&xh,  g_xh);
    cudaGetSymbolAddress((void**)&xl,  g_xl);
    cudaGetSymbolAddress((void**)&ath, g_ath);
    cudaGetSymbolAddress((void**)&atl, g_atl);
    cudaGetSymbolAddress((void**)&wth, g_wth);
    cudaGetSymbolAddress((void**)&wtl, g_wtl);

    // Box path (exact binary64 semantics): SUB_H=15, SUB_W=9
    Boxes bx;
    bx.sub_h = (int)((0.35 - 0.10) * 64.0);
    bx.sub_w = (int)((0.35 - 0.10) * 40.0);
    for (int t = 0; t < TT; t++) {
        double r  = (double)t / 15.0;
        double h0 = 0.10 + r * (0.60 - 0.10);
        double w0 = 0.10 + r * (0.60 - 0.10);
        bx.hs[t] = (int)(h0 * 64.0);
        bx.ws[t] = (int)(w0 * 40.0);
    }

    cudaFuncSetAttribute(gemm_bf, cudaFuncAttributeMaxDynamicSharedMemorySize, GDYN);

    split_x<<<MTOT * QD / 512, 256>>>(x, xh, xl);
    split_w<<<dim3(16, 16, 4), dim3(32, 8)>>>(Wq, Wk, Wv, Wo, wth, wtl);

    // fused QKV: blockIdx.z selects the weight / output
    gemm_bf<<<dim3(4, 320, 3), 256, GDYN>>>(xh, xl, wth, wtl, nullptr, q, k, v);

    attn_kernel<<<dim3(HW, HEADS), 256>>>(q, k, v, rel_k, rel_v, ath, atl, bx);

    // output projection: weight index 3
    gemm_bf<<<dim3(4, 320, 1), 256, GDYN>>>(ath, atl,
                                            wth + (size_t)3 * QD * QD,
                                            wtl + (size_t)3 * QD * QD,
                                            bo, out, out, out);
}